// round 2
// baseline (speedup 1.0000x reference)
#include <cuda_runtime.h>
#include <math.h>

#define B_    16
#define T_    400
#define DV_   4096
#define DS_   768
#define D_    1024
#define L_    32
#define NSEG  16
#define FPS_  25
#define NPROP 136

// ---------------- scratch (static device globals; no allocation) ----------------
__device__ float    g_Vr[B_ * T_ * D_];          // 26.2 MB
__device__ float    g_Sr[B_ * L_ * D_];          // 2.1 MB
__device__ float    g_scores[B_ * L_ * T_];      // 0.82 MB
__device__ float    g_wtil[B_ * L_ * T_];        // 0.82 MB
__device__ float    g_m[B_ * L_ * NSEG];
__device__ float    g_Zs[B_ * L_ * NSEG];
__device__ float    g_E[B_ * L_ * NSEG * D_];    // 33.5 MB
__device__ float    g_snorm[B_ * D_];
__device__ unsigned g_negmax[B_];

// ---------------- generic fp32 SGEMM C = A@B + bias, row-major ----------------
// BM=128, BN=64, BK=16, 256 threads, 8x4 micro-tile. M%128==0, N%64==0, K%16==0.
__global__ void sgemm_bias(const float* __restrict__ A, const float* __restrict__ Bm,
                           const float* __restrict__ bias, float* __restrict__ C,
                           int M, int N, int K)
{
    const int BK = 16;
    __shared__ float As[BK][132];   // [k][m], padded
    __shared__ float Bs[BK][68];    // [k][n], padded

    int tid = threadIdx.x;
    int m0 = blockIdx.y * 128, n0 = blockIdx.x * 64;
    int ty = tid >> 4, tx = tid & 15;       // ty: 8 rows, tx: 4 cols

    float acc[8][4];
#pragma unroll
    for (int i = 0; i < 8; i++)
#pragma unroll
        for (int j = 0; j < 4; j++) acc[i][j] = 0.f;

    int arow = tid >> 2, acol = (tid & 3) * 4;   // A tile: 128x16
    int brow = tid >> 4, bcol = (tid & 15) * 4;  // B tile: 16x64

    for (int k0 = 0; k0 < K; k0 += BK) {
#pragma unroll
        for (int i = 0; i < 2; i++) {
            float4 v = *(const float4*)&A[(long)(m0 + arow + i * 64) * K + k0 + acol];
            As[acol + 0][arow + i * 64] = v.x;
            As[acol + 1][arow + i * 64] = v.y;
            As[acol + 2][arow + i * 64] = v.z;
            As[acol + 3][arow + i * 64] = v.w;
        }
        {
            float4 v = *(const float4*)&Bm[(long)(k0 + brow) * N + n0 + bcol];
            Bs[brow][bcol + 0] = v.x; Bs[brow][bcol + 1] = v.y;
            Bs[brow][bcol + 2] = v.z; Bs[brow][bcol + 3] = v.w;
        }
        __syncthreads();
#pragma unroll
        for (int kk = 0; kk < BK; kk++) {
            float4 a0 = *(const float4*)&As[kk][ty * 8];
            float4 a1 = *(const float4*)&As[kk][ty * 8 + 4];
            float4 bq = *(const float4*)&Bs[kk][tx * 4];
            float a[8] = {a0.x, a0.y, a0.z, a0.w, a1.x, a1.y, a1.z, a1.w};
            float bb[4] = {bq.x, bq.y, bq.z, bq.w};
#pragma unroll
            for (int i = 0; i < 8; i++)
#pragma unroll
                for (int j = 0; j < 4; j++) acc[i][j] += a[i] * bb[j];
        }
        __syncthreads();
    }

    float4 bb = *(const float4*)&bias[n0 + tx * 4];
#pragma unroll
    for (int i = 0; i < 8; i++) {
        float4 o;
        o.x = acc[i][0] + bb.x; o.y = acc[i][1] + bb.y;
        o.z = acc[i][2] + bb.z; o.w = acc[i][3] + bb.w;
        *(float4*)&C[(long)(m0 + ty * 8 + i) * N + n0 + tx * 4] = o;
    }
}

// ---------------- Sr row norms over L: snorm[b,d] = ||Sr[b,:,d]||2 ----------------
__global__ void snorm_kernel()
{
    int id = blockIdx.x * 256 + threadIdx.x;    // 16384 total
    int b = id >> 10, d = id & 1023;
    float s = 0.f;
#pragma unroll
    for (int l = 0; l < L_; l++) {
        float v = g_Sr[(b * L_ + l) * D_ + d];
        s += v * v;
    }
    g_snorm[id] = sqrtf(s);
}

// ---------------- scores[b,l,t] = Sr[b,l,:]·Vr[b,t,:]  (NT GEMM, K=1024) ----------------
__global__ void scores_kernel()
{
    int b = blockIdx.y;
    int t0 = blockIdx.x * 64;
    __shared__ float sS[32][36];   // [k][l]
    __shared__ float sV[32][68];   // [k][t]
    int tid = threadIdx.x;
    int ty = tid >> 4, tx = tid & 15;
    float acc[2][4] = {{0, 0, 0, 0}, {0, 0, 0, 0}};

    int lrow = tid >> 3, kc = (tid & 7) * 4;
    for (int k0 = 0; k0 < D_; k0 += 32) {
        {
            float4 v = *(const float4*)&g_Sr[(b * L_ + lrow) * D_ + k0 + kc];
            sS[kc + 0][lrow] = v.x; sS[kc + 1][lrow] = v.y;
            sS[kc + 2][lrow] = v.z; sS[kc + 3][lrow] = v.w;
        }
#pragma unroll
        for (int i = 0; i < 2; i++) {
            int tt = lrow + i * 32;
            int t = t0 + tt;
            float4 w = make_float4(0.f, 0.f, 0.f, 0.f);
            if (t < T_) w = *(const float4*)&g_Vr[((long)b * T_ + t) * D_ + k0 + kc];
            sV[kc + 0][tt] = w.x; sV[kc + 1][tt] = w.y;
            sV[kc + 2][tt] = w.z; sV[kc + 3][tt] = w.w;
        }
        __syncthreads();
#pragma unroll
        for (int kk = 0; kk < 32; kk++) {
            float a0 = sS[kk][ty * 2], a1 = sS[kk][ty * 2 + 1];
            float4 bv = *(const float4*)&sV[kk][tx * 4];
            acc[0][0] += a0 * bv.x; acc[0][1] += a0 * bv.y;
            acc[0][2] += a0 * bv.z; acc[0][3] += a0 * bv.w;
            acc[1][0] += a1 * bv.x; acc[1][1] += a1 * bv.y;
            acc[1][2] += a1 * bv.z; acc[1][3] += a1 * bv.w;
        }
        __syncthreads();
    }
#pragma unroll
    for (int i = 0; i < 2; i++) {
        int l = ty * 2 + i;
#pragma unroll
        for (int j = 0; j < 4; j++) {
            int t = t0 + tx * 4 + j;
            if (t < T_) g_scores[(b * L_ + l) * T_ + t] = acc[i][j];
        }
    }
}

// ---------------- per-segment max/Z + exp weights ----------------
__global__ void segprep_kernel()
{
    int bl = blockIdx.x;            // 0..511 = (b*L + l)
    __shared__ float sm[NSEG];
    int tid = threadIdx.x;          // 256
    const float* row = g_scores + bl * T_;
    if (tid < NSEG) {
        float mx = -INFINITY;
#pragma unroll
        for (int i = 0; i < FPS_; i++) mx = fmaxf(mx, row[tid * FPS_ + i]);
        float z = 0.f;
#pragma unroll
        for (int i = 0; i < FPS_; i++) z += expf(row[tid * FPS_ + i] - mx);
        sm[tid] = mx;
        g_m[bl * NSEG + tid] = mx;
        g_Zs[bl * NSEG + tid] = z;
    }
    __syncthreads();
    for (int t = tid; t < T_; t += 256)
        g_wtil[bl * T_ + t] = expf(row[t] - sm[t / FPS_]);
}

// ---------------- E[b,l,g,d] = sum_{t in seg g} wtil * Vr[b,t,d] ----------------
__global__ void eagg_kernel()
{
    int dc = blockIdx.x, g = blockIdx.y, b = blockIdx.z;   // (4, 16, 16)
    int tid = threadIdx.x;     // 256
    int d = dc * 256 + tid;
    __shared__ float Vs[FPS_][256];
    __shared__ float ws[L_][FPS_ + 1];
#pragma unroll
    for (int t = 0; t < FPS_; t++)
        Vs[t][tid] = g_Vr[((long)b * T_ + g * FPS_ + t) * D_ + d];
    for (int i = tid; i < L_ * FPS_; i += 256) {
        int l = i / FPS_, t = i % FPS_;
        ws[l][t] = g_wtil[(b * L_ + l) * T_ + g * FPS_ + t];
    }
    __syncthreads();
    for (int l = 0; l < L_; l++) {
        float acc = 0.f;
#pragma unroll
        for (int t = 0; t < FPS_; t++) acc += ws[l][t] * Vs[t][tid];
        g_E[((long)(b * L_ + l) * NSEG + g) * D_ + d] = acc;
    }
}

// ---------------- per-proposal scoring + positive/negative reduction ----------------
__global__ void prop_kernel(const int* __restrict__ ytrue, float* __restrict__ outPos)
{
    int p = blockIdx.x;     // 136
    int b = blockIdx.y;     // 16
    int tid = threadIdx.x;  // 256

    int s = 0, rem = p;
    while (rem >= NSEG - s) { rem -= NSEG - s; s++; }
    int e = s + rem;

    int ys = ytrue[2 * b], ye = ytrue[2 * b + 1];
    int pstar = ys * NSEG - (ys * (ys - 1)) / 2 + (ye - ys);
    bool isp = (p == pstar);

    __shared__ float alpha[L_][NSEG];
    __shared__ float invZ[L_];
    if (tid < L_) {
        int l = tid;
        const float* mrow = g_m + (b * L_ + l) * NSEG;
        const float* zrow = g_Zs + (b * L_ + l) * NSEG;
        float M = -INFINITY;
        for (int g = s; g <= e; g++) M = fmaxf(M, mrow[g]);
        float Zw = 0.f;
        for (int g = s; g <= e; g++) {
            float a = expf(mrow[g] - M);
            alpha[l][g] = a;
            Zw += a * zrow[g];
        }
        invZ[l] = 1.0f / Zw;
    }
    __syncthreads();

    float num[4] = {0, 0, 0, 0}, sq[4] = {0, 0, 0, 0};
    for (int l = 0; l < L_; l++) {
        float o[4] = {0, 0, 0, 0};
        const float* Eb = g_E + ((long)(b * L_ + l) * NSEG) * D_ + tid;
        for (int g = s; g <= e; g++) {
            float a = alpha[l][g];
#pragma unroll
            for (int j = 0; j < 4; j++) o[j] += a * Eb[g * D_ + j * 256];
        }
        float iz = invZ[l];
        const float* srow = g_Sr + (b * L_ + l) * D_ + tid;
#pragma unroll
        for (int j = 0; j < 4; j++) {
            float oo = o[j] * iz;
            float sv = srow[j * 256];
            num[j] += oo * sv;
            sq[j] += oo * oo;
        }
    }

    float lmax = -INFINITY;
#pragma unroll
    for (int j = 0; j < 4; j++) {
        int d = tid + j * 256;
        float scv = num[j] / (sqrtf(sq[j]) * g_snorm[b * D_ + d] + 1e-15f);
        if (isp) outPos[b * D_ + d] = scv;
        else lmax = fmaxf(lmax, scv);
    }

    if (!isp) {
#pragma unroll
        for (int off = 16; off; off >>= 1)
            lmax = fmaxf(lmax, __shfl_xor_sync(0xffffffffu, lmax, off));
        __shared__ float wmax[8];
        if ((tid & 31) == 0) wmax[tid >> 5] = lmax;
        __syncthreads();
        if (tid < 8) {
            float v = wmax[tid];
#pragma unroll
            for (int off = 4; off; off >>= 1)
                v = fmaxf(v, __shfl_xor_sync(0x000000ffu, v, off));
            if (tid == 0) {
                unsigned u = __float_as_uint(v);
                u = (u & 0x80000000u) ? ~u : (u | 0x80000000u);
                atomicMax(&g_negmax[b], u);
            }
        }
    }
}

__global__ void init_neg()
{
    if (threadIdx.x < B_) g_negmax[threadIdx.x] = 0x007FFFFFu;  // enc(-inf)
}

__global__ void fin_kernel(float* __restrict__ outNeg)
{
    int b = threadIdx.x;
    if (b < B_) {
        unsigned u = g_negmax[b];
        unsigned bits = (u & 0x80000000u) ? (u ^ 0x80000000u) : ~u;
        outNeg[b] = __uint_as_float(bits);
    }
}

// ---------------- launch ----------------
extern "C" void kernel_launch(void* const* d_in, const int* in_sizes, int n_in,
                              void* d_out, int out_size)
{
    const float* videos    = (const float*)d_in[0];
    const float* sentences = (const float*)d_in[1];
    const float* Wv        = (const float*)d_in[2];
    const float* bv        = (const float*)d_in[3];
    const float* Ws        = (const float*)d_in[4];
    const float* bs        = (const float*)d_in[5];
    const int*   ytrue     = (const int*)d_in[6];
    float* out = (float*)d_out;

    float *pVr = nullptr, *pSr = nullptr;
    cudaGetSymbolAddress((void**)&pVr, g_Vr);
    cudaGetSymbolAddress((void**)&pSr, g_Sr);

    init_neg<<<1, 32>>>();

    // Sr = sentences @ Ws + bs   [512,768]x[768,1024]
    sgemm_bias<<<dim3(D_ / 64, (B_ * L_) / 128), 256>>>(sentences, Ws, bs, pSr,
                                                        B_ * L_, D_, DS_);
    // Vr = videos @ Wv + bv      [6400,4096]x[4096,1024]
    sgemm_bias<<<dim3(D_ / 64, (B_ * T_) / 128), 256>>>(videos, Wv, bv, pVr,
                                                        B_ * T_, D_, DV_);

    snorm_kernel<<<(B_ * D_) / 256, 256>>>();
    scores_kernel<<<dim3((T_ + 63) / 64, B_), 256>>>();
    segprep_kernel<<<B_ * L_, 256>>>();
    eagg_kernel<<<dim3(D_ / 256, NSEG, B_), 256>>>();
    prop_kernel<<<dim3(NPROP, B_), 256>>>(ytrue, out);
    fin_kernel<<<1, 32>>>(out + B_ * D_);
}

// round 4
// speedup vs baseline: 2.0782x; 2.0782x over previous
#include <cuda_runtime.h>
#include <cuda_bf16.h>
#include <math.h>
#include <stdint.h>

#define B_    16
#define T_    400
#define DV_   4096
#define DS_   768
#define D_    1024
#define L_    32
#define NSEG  16
#define FPS_  25
#define NPROP 136

// ---------------- scratch (static device globals; no allocation) ----------------
__device__ float    g_Vr[B_ * T_ * D_];          // 26.2 MB
__device__ float    g_Sr[B_ * L_ * D_];          // 2.1 MB
__device__ float    g_scores[B_ * L_ * T_];
__device__ float    g_wtil[B_ * L_ * T_];
__device__ float    g_m[B_ * L_ * NSEG];
__device__ float    g_Zs[B_ * L_ * NSEG];
__device__ float    g_E[B_ * L_ * NSEG * D_];    // 33.5 MB
__device__ float    g_snorm[B_ * D_];
__device__ unsigned g_negmax[B_];

// split-bf16 operands for the big GEMM
__device__ __align__(16) __nv_bfloat16 g_Ahi[(long)B_ * T_ * DV_];  // [M,K]
__device__ __align__(16) __nv_bfloat16 g_Alo[(long)B_ * T_ * DV_];
__device__ __align__(16) __nv_bfloat16 g_Bhi[(long)D_ * DV_];       // [N,K]
__device__ __align__(16) __nv_bfloat16 g_Blo[(long)D_ * DV_];

// ---------------- helpers ----------------
__device__ __forceinline__ uint32_t smem_u32(const void* p) {
    uint32_t a;
    asm("{ .reg .u64 t; cvta.to.shared.u64 t, %1; cvt.u32.u64 %0, t; }" : "=r"(a) : "l"(p));
    return a;
}
#define CP_ASYNC16(dst, src) \
    asm volatile("cp.async.cg.shared.global [%0], [%1], 16;" :: "r"(dst), "l"(src) : "memory")
#define CP_COMMIT() asm volatile("cp.async.commit_group;" ::: "memory")
#define CP_WAIT(n)  asm volatile("cp.async.wait_group %0;" :: "n"(n) : "memory")

__device__ __forceinline__ void mma16816(float* c, const uint32_t* a, const uint32_t* b) {
    asm volatile(
        "mma.sync.aligned.m16n8k16.row.col.f32.bf16.bf16.f32 "
        "{%0,%1,%2,%3}, {%4,%5,%6,%7}, {%8,%9}, {%0,%1,%2,%3};"
        : "+f"(c[0]), "+f"(c[1]), "+f"(c[2]), "+f"(c[3])
        : "r"(a[0]), "r"(a[1]), "r"(a[2]), "r"(a[3]), "r"(b[0]), "r"(b[1]));
}

// ============================================================================
// Vr GEMM: C[6400,1024] = A(split bf16)[M,K] @ B(split bf16)[N,K]^T + bias
// 128x128 tile, BK=32, cp.async double buffer, mma.sync m16n8k16 bf16 (3-term)
// ============================================================================
#define BK      32
#define LDT     40                        // bf16 per row in smem (32 + 8 pad)
#define TILE_B  (128 * LDT * 2)           // 10240 bytes per matrix tile
#define STAGE_B (4 * TILE_B)              // 40960: Ah, Al, Bh, Bl
#define GEMM_SMEM (2 * STAGE_B)           // 81920

__device__ __forceinline__ void load_stage(
    uint32_t sbase,
    const __nv_bfloat16* __restrict__ Ah, const __nv_bfloat16* __restrict__ Al,
    const __nv_bfloat16* __restrict__ Bh, const __nv_bfloat16* __restrict__ Bl,
    int m0, int n0, int k0, int tid)
{
#pragma unroll
    for (int i = 0; i < 8; i++) {
        int c = i * 256 + tid;
        int mat = c >> 9;              // 0:Ah 1:Al 2:Bh 3:Bl
        int rem = c & 511;
        int row = rem >> 2;
        int ch  = rem & 3;
        const __nv_bfloat16* gp;
        long roff;
        if (mat == 0)      { gp = Ah; roff = (long)(m0 + row) * DV_; }
        else if (mat == 1) { gp = Al; roff = (long)(m0 + row) * DV_; }
        else if (mat == 2) { gp = Bh; roff = (long)(n0 + row) * DV_; }
        else               { gp = Bl; roff = (long)(n0 + row) * DV_; }
        roff += k0 + ch * 8;
        uint32_t dst = sbase + mat * TILE_B + row * (LDT * 2) + ch * 16;
        CP_ASYNC16(dst, gp + roff);
    }
}

__global__ void __launch_bounds__(256) vr_gemm(
    const __nv_bfloat16* __restrict__ Ah, const __nv_bfloat16* __restrict__ Al,
    const __nv_bfloat16* __restrict__ Bh, const __nv_bfloat16* __restrict__ Bl,
    const float* __restrict__ bias, float* __restrict__ C)
{
    extern __shared__ char smc[];
    uint32_t sb = smem_u32(smc);
    int tid = threadIdx.x, wid = tid >> 5, lane = tid & 31;
    int g = lane >> 2, tig = lane & 3;
    int wm = wid >> 2, wn = wid & 3;          // 2 x 4 warp grid
    int n0 = blockIdx.x * 128, m0 = blockIdx.y * 128;

    float acc[4][4][4];
#pragma unroll
    for (int a = 0; a < 4; a++)
#pragma unroll
        for (int b = 0; b < 4; b++)
#pragma unroll
            for (int cc = 0; cc < 4; cc++) acc[a][b][cc] = 0.f;

    load_stage(sb, Ah, Al, Bh, Bl, m0, n0, 0, tid);
    CP_COMMIT();

    const int NKT = DV_ / BK;   // 128
    for (int kt = 0; kt < NKT; kt++) {
        if (kt + 1 < NKT) {
            load_stage(sb + ((kt + 1) & 1) * STAGE_B, Ah, Al, Bh, Bl,
                       m0, n0, (kt + 1) * BK, tid);
            CP_COMMIT();
            CP_WAIT(1);
        } else {
            CP_WAIT(0);
        }
        __syncthreads();

        const char* st = smc + (kt & 1) * STAGE_B;
        const uint32_t* pAh = (const uint32_t*)(st);
        const uint32_t* pAl = (const uint32_t*)(st + TILE_B);
        const uint32_t* pBh = (const uint32_t*)(st + 2 * TILE_B);
        const uint32_t* pBl = (const uint32_t*)(st + 3 * TILE_B);

#pragma unroll
        for (int ks = 0; ks < 2; ks++) {
            int kw = ks * 8 + tig;
            uint32_t bh[4][2], bl[4][2];
#pragma unroll
            for (int ni = 0; ni < 4; ni++) {
                int n = wn * 32 + ni * 8 + g;
                int w = n * (LDT / 2) + kw;
                bh[ni][0] = pBh[w]; bh[ni][1] = pBh[w + 4];
                bl[ni][0] = pBl[w]; bl[ni][1] = pBl[w + 4];
            }
#pragma unroll
            for (int mi = 0; mi < 4; mi++) {
                int r = wm * 64 + mi * 16 + g;
                int w0 = r * (LDT / 2) + kw;
                int w1 = (r + 8) * (LDT / 2) + kw;
                uint32_t ah[4] = {pAh[w0], pAh[w1], pAh[w0 + 4], pAh[w1 + 4]};
                uint32_t al[4] = {pAl[w0], pAl[w1], pAl[w0 + 4], pAl[w1 + 4]};
#pragma unroll
                for (int ni = 0; ni < 4; ni++) {
                    mma16816(acc[mi][ni], ah, bh[ni]);
                    mma16816(acc[mi][ni], ah, bl[ni]);
                    mma16816(acc[mi][ni], al, bh[ni]);
                }
            }
        }
        __syncthreads();
    }

    // epilogue: C[m, n] = acc + bias[n]
#pragma unroll
    for (int mi = 0; mi < 4; mi++) {
        int mA = m0 + wm * 64 + mi * 16 + g;
#pragma unroll
        for (int ni = 0; ni < 4; ni++) {
            int n = n0 + wn * 32 + ni * 8 + tig * 2;
            float b0 = bias[n], b1 = bias[n + 1];
            float2 v0 = make_float2(acc[mi][ni][0] + b0, acc[mi][ni][1] + b1);
            float2 v1 = make_float2(acc[mi][ni][2] + b0, acc[mi][ni][3] + b1);
            *(float2*)&C[(long)mA * D_ + n] = v0;
            *(float2*)&C[(long)(mA + 8) * D_ + n] = v1;
        }
    }
}

// ---------------- split fp32 -> (hi, lo) bf16 ----------------
__global__ void splitA_kernel(const float* __restrict__ A,
                              __nv_bfloat16* __restrict__ hi, __nv_bfloat16* __restrict__ lo)
{
    long i = ((long)blockIdx.x * 256 + threadIdx.x) * 4;
    float4 v = *(const float4*)(A + i);
    float x[4] = {v.x, v.y, v.z, v.w};
    __nv_bfloat16 h[4], l[4];
#pragma unroll
    for (int j = 0; j < 4; j++) {
        h[j] = __float2bfloat16(x[j]);
        l[j] = __float2bfloat16(x[j] - __bfloat162float(h[j]));
    }
    __nv_bfloat162 h01; h01.x = h[0]; h01.y = h[1];
    __nv_bfloat162 h23; h23.x = h[2]; h23.y = h[3];
    __nv_bfloat162 l01; l01.x = l[0]; l01.y = l[1];
    __nv_bfloat162 l23; l23.x = l[2]; l23.y = l[3];
    *(__nv_bfloat162*)(hi + i) = h01;
    *(__nv_bfloat162*)(hi + i + 2) = h23;
    *(__nv_bfloat162*)(lo + i) = l01;
    *(__nv_bfloat162*)(lo + i + 2) = l23;
}

// W [K=4096, N=1024] fp32 -> transposed split bf16 [N, K]
__global__ void splitW_kernel(const float* __restrict__ W,
                              __nv_bfloat16* __restrict__ hi, __nv_bfloat16* __restrict__ lo)
{
    __shared__ float t[32][33];
    int k0 = blockIdx.x * 32, n0 = blockIdx.y * 32;
    int tx = threadIdx.x, ty = threadIdx.y;
#pragma unroll
    for (int i = 0; i < 32; i += 8)
        t[ty + i][tx] = W[(long)(k0 + ty + i) * D_ + n0 + tx];
    __syncthreads();
#pragma unroll
    for (int i = 0; i < 32; i += 8) {
        int n = n0 + ty + i, k = k0 + tx;
        float x = t[tx][ty + i];
        __nv_bfloat16 h = __float2bfloat16(x);
        hi[(long)n * DV_ + k] = h;
        lo[(long)n * DV_ + k] = __float2bfloat16(x - __bfloat162float(h));
    }
}

// ---------------- fp32 SGEMM (kept for Sr) ----------------
__global__ void sgemm_bias(const float* __restrict__ A, const float* __restrict__ Bm,
                           const float* __restrict__ bias, float* __restrict__ C,
                           int M, int N, int K)
{
    const int BKs = 16;
    __shared__ float As[BKs][132];
    __shared__ float Bs[BKs][68];

    int tid = threadIdx.x;
    int m0 = blockIdx.y * 128, n0 = blockIdx.x * 64;
    int ty = tid >> 4, tx = tid & 15;

    float acc[8][4];
#pragma unroll
    for (int i = 0; i < 8; i++)
#pragma unroll
        for (int j = 0; j < 4; j++) acc[i][j] = 0.f;

    int arow = tid >> 2, acol = (tid & 3) * 4;
    int brow = tid >> 4, bcol = (tid & 15) * 4;

    for (int k0 = 0; k0 < K; k0 += BKs) {
#pragma unroll
        for (int i = 0; i < 2; i++) {
            float4 v = *(const float4*)&A[(long)(m0 + arow + i * 64) * K + k0 + acol];
            As[acol + 0][arow + i * 64] = v.x;
            As[acol + 1][arow + i * 64] = v.y;
            As[acol + 2][arow + i * 64] = v.z;
            As[acol + 3][arow + i * 64] = v.w;
        }
        {
            float4 v = *(const float4*)&Bm[(long)(k0 + brow) * N + n0 + bcol];
            Bs[brow][bcol + 0] = v.x; Bs[brow][bcol + 1] = v.y;
            Bs[brow][bcol + 2] = v.z; Bs[brow][bcol + 3] = v.w;
        }
        __syncthreads();
#pragma unroll
        for (int kk = 0; kk < BKs; kk++) {
            float4 a0 = *(const float4*)&As[kk][ty * 8];
            float4 a1 = *(const float4*)&As[kk][ty * 8 + 4];
            float4 bq = *(const float4*)&Bs[kk][tx * 4];
            float a[8] = {a0.x, a0.y, a0.z, a0.w, a1.x, a1.y, a1.z, a1.w};
            float bb[4] = {bq.x, bq.y, bq.z, bq.w};
#pragma unroll
            for (int i = 0; i < 8; i++)
#pragma unroll
                for (int j = 0; j < 4; j++) acc[i][j] += a[i] * bb[j];
        }
        __syncthreads();
    }

    float4 bb = *(const float4*)&bias[n0 + tx * 4];
#pragma unroll
    for (int i = 0; i < 8; i++) {
        float4 o;
        o.x = acc[i][0] + bb.x; o.y = acc[i][1] + bb.y;
        o.z = acc[i][2] + bb.z; o.w = acc[i][3] + bb.w;
        *(float4*)&C[(long)(m0 + ty * 8 + i) * N + n0 + tx * 4] = o;
    }
}

// ---------------- Sr column norms ----------------
__global__ void snorm_kernel()
{
    int id = blockIdx.x * 256 + threadIdx.x;
    int b = id >> 10, d = id & 1023;
    float s = 0.f;
#pragma unroll
    for (int l = 0; l < L_; l++) {
        float v = g_Sr[(b * L_ + l) * D_ + d];
        s += v * v;
    }
    g_snorm[id] = sqrtf(s);
}

// ---------------- scores[b,l,t] = Sr[b,l,:]·Vr[b,t,:] ----------------
__global__ void scores_kernel()
{
    int b = blockIdx.y;
    int t0 = blockIdx.x * 64;
    __shared__ float sS[32][36];
    __shared__ float sV[32][68];
    int tid = threadIdx.x;
    int ty = tid >> 4, tx = tid & 15;
    float acc[2][4] = {{0, 0, 0, 0}, {0, 0, 0, 0}};

    int lrow = tid >> 3, kc = (tid & 7) * 4;
    for (int k0 = 0; k0 < D_; k0 += 32) {
        {
            float4 v = *(const float4*)&g_Sr[(b * L_ + lrow) * D_ + k0 + kc];
            sS[kc + 0][lrow] = v.x; sS[kc + 1][lrow] = v.y;
            sS[kc + 2][lrow] = v.z; sS[kc + 3][lrow] = v.w;
        }
#pragma unroll
        for (int i = 0; i < 2; i++) {
            int tt = lrow + i * 32;
            int t = t0 + tt;
            float4 w = make_float4(0.f, 0.f, 0.f, 0.f);
            if (t < T_) w = *(const float4*)&g_Vr[((long)b * T_ + t) * D_ + k0 + kc];
            sV[kc + 0][tt] = w.x; sV[kc + 1][tt] = w.y;
            sV[kc + 2][tt] = w.z; sV[kc + 3][tt] = w.w;
        }
        __syncthreads();
#pragma unroll
        for (int kk = 0; kk < 32; kk++) {
            float a0 = sS[kk][ty * 2], a1 = sS[kk][ty * 2 + 1];
            float4 bv = *(const float4*)&sV[kk][tx * 4];
            acc[0][0] += a0 * bv.x; acc[0][1] += a0 * bv.y;
            acc[0][2] += a0 * bv.z; acc[0][3] += a0 * bv.w;
            acc[1][0] += a1 * bv.x; acc[1][1] += a1 * bv.y;
            acc[1][2] += a1 * bv.z; acc[1][3] += a1 * bv.w;
        }
        __syncthreads();
    }
#pragma unroll
    for (int i = 0; i < 2; i++) {
        int l = ty * 2 + i;
#pragma unroll
        for (int j = 0; j < 4; j++) {
            int t = t0 + tx * 4 + j;
            if (t < T_) g_scores[(b * L_ + l) * T_ + t] = acc[i][j];
        }
    }
}

// ---------------- per-segment max/Z + exp weights ----------------
__global__ void segprep_kernel()
{
    int bl = blockIdx.x;
    __shared__ float sm[NSEG];
    int tid = threadIdx.x;
    const float* row = g_scores + bl * T_;
    if (tid < NSEG) {
        float mx = -INFINITY;
#pragma unroll
        for (int i = 0; i < FPS_; i++) mx = fmaxf(mx, row[tid * FPS_ + i]);
        float z = 0.f;
#pragma unroll
        for (int i = 0; i < FPS_; i++) z += expf(row[tid * FPS_ + i] - mx);
        sm[tid] = mx;
        g_m[bl * NSEG + tid] = mx;
        g_Zs[bl * NSEG + tid] = z;
    }
    __syncthreads();
    for (int t = tid; t < T_; t += 256)
        g_wtil[bl * T_ + t] = expf(row[t] - sm[t / FPS_]);
}

// ---------------- E[b,l,g,d] = sum_{t in seg g} wtil * Vr[b,t,d] ----------------
__global__ void eagg_kernel()
{
    int dc = blockIdx.x, g = blockIdx.y, b = blockIdx.z;
    int tid = threadIdx.x;
    int d = dc * 256 + tid;
    __shared__ float Vs[FPS_][256];
    __shared__ float ws[L_][FPS_ + 1];
#pragma unroll
    for (int t = 0; t < FPS_; t++)
        Vs[t][tid] = g_Vr[((long)b * T_ + g * FPS_ + t) * D_ + d];
    for (int i = tid; i < L_ * FPS_; i += 256) {
        int l = i / FPS_, t = i % FPS_;
        ws[l][t] = g_wtil[(b * L_ + l) * T_ + g * FPS_ + t];
    }
    __syncthreads();
    for (int l = 0; l < L_; l++) {
        float acc = 0.f;
#pragma unroll
        for (int t = 0; t < FPS_; t++) acc += ws[l][t] * Vs[t][tid];
        g_E[((long)(b * L_ + l) * NSEG + g) * D_ + d] = acc;
    }
}

// ---------------- per-proposal scoring + reductions ----------------
__global__ void prop_kernel(const int* __restrict__ ytrue, float* __restrict__ outPos)
{
    int p = blockIdx.x;
    int b = blockIdx.y;
    int tid = threadIdx.x;

    int s = 0, rem = p;
    while (rem >= NSEG - s) { rem -= NSEG - s; s++; }
    int e = s + rem;

    int ys = ytrue[2 * b], ye = ytrue[2 * b + 1];
    int pstar = ys * NSEG - (ys * (ys - 1)) / 2 + (ye - ys);
    bool isp = (p == pstar);

    __shared__ float alpha[L_][NSEG];
    __shared__ float invZ[L_];
    if (tid < L_) {
        int l = tid;
        const float* mrow = g_m + (b * L_ + l) * NSEG;
        const float* zrow = g_Zs + (b * L_ + l) * NSEG;
        float M = -INFINITY;
        for (int g = s; g <= e; g++) M = fmaxf(M, mrow[g]);
        float Zw = 0.f;
        for (int g = s; g <= e; g++) {
            float a = expf(mrow[g] - M);
            alpha[l][g] = a;
            Zw += a * zrow[g];
        }
        invZ[l] = 1.0f / Zw;
    }
    __syncthreads();

    float num[4] = {0, 0, 0, 0}, sq[4] = {0, 0, 0, 0};
    for (int l = 0; l < L_; l++) {
        float o[4] = {0, 0, 0, 0};
        const float* Eb = g_E + ((long)(b * L_ + l) * NSEG) * D_ + tid;
        for (int g = s; g <= e; g++) {
            float a = alpha[l][g];
#pragma unroll
            for (int j = 0; j < 4; j++) o[j] += a * Eb[g * D_ + j * 256];
        }
        float iz = invZ[l];
        const float* srow = g_Sr + (b * L_ + l) * D_ + tid;
#pragma unroll
        for (int j = 0; j < 4; j++) {
            float oo = o[j] * iz;
            float sv = srow[j * 256];
            num[j] += oo * sv;
            sq[j] += oo * oo;
        }
    }

    float lmax = -INFINITY;
#pragma unroll
    for (int j = 0; j < 4; j++) {
        int d = tid + j * 256;
        float scv = num[j] / (sqrtf(sq[j]) * g_snorm[b * D_ + d] + 1e-15f);
        if (isp) outPos[b * D_ + d] = scv;
        else lmax = fmaxf(lmax, scv);
    }

    if (!isp) {
#pragma unroll
        for (int off = 16; off; off >>= 1)
            lmax = fmaxf(lmax, __shfl_xor_sync(0xffffffffu, lmax, off));
        __shared__ float wmax[8];
        if ((tid & 31) == 0) wmax[tid >> 5] = lmax;
        __syncthreads();
        if (tid < 8) {
            float v = wmax[tid];
#pragma unroll
            for (int off = 4; off; off >>= 1)
                v = fmaxf(v, __shfl_xor_sync(0x000000ffu, v, off));
            if (tid == 0) {
                unsigned u = __float_as_uint(v);
                u = (u & 0x80000000u) ? ~u : (u | 0x80000000u);
                atomicMax(&g_negmax[b], u);
            }
        }
    }
}

__global__ void init_neg()
{
    if (threadIdx.x < B_) g_negmax[threadIdx.x] = 0x007FFFFFu;
}

__global__ void fin_kernel(float* __restrict__ outNeg)
{
    int b = threadIdx.x;
    if (b < B_) {
        unsigned u = g_negmax[b];
        unsigned bits = (u & 0x80000000u) ? (u ^ 0x80000000u) : ~u;
        outNeg[b] = __uint_as_float(bits);
    }
}

// ---------------- launch ----------------
extern "C" void kernel_launch(void* const* d_in, const int* in_sizes, int n_in,
                              void* d_out, int out_size)
{
    const float* videos    = (const float*)d_in[0];
    const float* sentences = (const float*)d_in[1];
    const float* Wv        = (const float*)d_in[2];
    const float* bv        = (const float*)d_in[3];
    const float* Ws        = (const float*)d_in[4];
    const float* bs        = (const float*)d_in[5];
    const int*   ytrue     = (const int*)d_in[6];
    float* out = (float*)d_out;

    float *pVr = nullptr, *pSr = nullptr;
    void *pAhi = nullptr, *pAlo = nullptr, *pBhi = nullptr, *pBlo = nullptr;
    cudaGetSymbolAddress((void**)&pVr, g_Vr);
    cudaGetSymbolAddress((void**)&pSr, g_Sr);
    cudaGetSymbolAddress(&pAhi, g_Ahi);
    cudaGetSymbolAddress(&pAlo, g_Alo);
    cudaGetSymbolAddress(&pBhi, g_Bhi);
    cudaGetSymbolAddress(&pBlo, g_Blo);

    cudaFuncSetAttribute(vr_gemm, cudaFuncAttributeMaxDynamicSharedMemorySize, GEMM_SMEM);

    init_neg<<<1, 32>>>();

    // split conversions
    splitA_kernel<<<(int)(((long)B_ * T_ * DV_) / (256 * 4)), 256>>>(videos,
        (__nv_bfloat16*)pAhi, (__nv_bfloat16*)pAlo);
    splitW_kernel<<<dim3(DV_ / 32, D_ / 32), dim3(32, 8)>>>(Wv,
        (__nv_bfloat16*)pBhi, (__nv_bfloat16*)pBlo);

    // Sr = sentences @ Ws + bs (fp32)
    sgemm_bias<<<dim3(D_ / 64, (B_ * L_) / 128), 256>>>(sentences, Ws, bs, pSr,
                                                        B_ * L_, D_, DS_);

    // Vr = videos @ Wv + bv (tensor cores, split bf16, mma.sync)
    vr_gemm<<<dim3(D_ / 128, (B_ * T_) / 128), 256, GEMM_SMEM>>>(
        (const __nv_bfloat16*)pAhi, (const __nv_bfloat16*)pAlo,
        (const __nv_bfloat16*)pBhi, (const __nv_bfloat16*)pBlo, bv, pVr);

    snorm_kernel<<<(B_ * D_) / 256, 256>>>();
    scores_kernel<<<dim3((T_ + 63) / 64, B_), 256>>>();
    segprep_kernel<<<B_ * L_, 256>>>();
    eagg_kernel<<<dim3(D_ / 256, NSEG, B_), 256>>>();
    prop_kernel<<<dim3(NPROP, B_), 256>>>(ytrue, out);
    fin_kernel<<<1, 32>>>(out + B_ * D_);
}